// round 4
// baseline (speedup 1.0000x reference)
#include <cuda_runtime.h>
#include <cuda_bf16.h>
#include <string.h>

// Problem constants
#define BB 4096
#define SS 200
#define DD 64
#define HH 36
#define NROWS (BB * SS)          // 819200
#define BN_EPS 1e-5f
#define DICE_EPS 1e-3f

// ---------------- device scratch (no cudaMalloc allowed) ----------------
__device__ float g_WbcT[HH * DD];         // (B - C)^T   [h][d]
__device__ float g_WdT [HH * DD];         // D^T         [h][d]
__device__ float g_WacT[HH * DD];         // (A + C)^T   [h][d]
__device__ float g_partS[BB * HH];        // per-block per-feature partial sums
__device__ float g_partQ[BB * HH];        // per-block per-feature partial sumsq
__device__ float g_scaleA[HH];            // istd * gamma
__device__ float g_shiftC[HH];            // beta - mu * istd * gamma

// packed f32x2 FMA (Blackwell double-rate fp32 path; ptxas won't auto-fuse)
__device__ __forceinline__ void ffma2(float2& d, float2 a, float2 b) {
    unsigned long long ua, ub, ud;
    memcpy(&ua, &a, 8); memcpy(&ub, &b, 8); memcpy(&ud, &d, 8);
    asm("fma.rn.f32x2 %0, %1, %2, %0;" : "+l"(ud) : "l"(ua), "l"(ub));
    memcpy(&d, &ud, 8);
}

// ---------------- kernel 0: precompute weight combos ----------------
__global__ void k_init(const float* __restrict__ W1) {
    int t = threadIdx.x;
    for (int i = t; i < HH * DD; i += 256) {
        int h = i >> 6, d = i & 63;
        // W1 is [256][36] row-major; blocks: A rows 0-63, B 64-127, C 128-191, D 192-255
        float wA = W1[(d      ) * HH + h];
        float wB = W1[(64  + d) * HH + h];
        float wC = W1[(128 + d) * HH + h];
        float wD = W1[(192 + d) * HH + h];
        g_WbcT[i] = wB - wC;
        g_WdT [i] = wD;
        g_WacT[i] = wA + wC;
    }
}

// ---------------- kernel 1: per-b GEMM (200x64x36) -> smem tile -> stats only ----------------
__global__ __launch_bounds__(224, 3)
void k_pass1(const float* __restrict__ history,
             const float* __restrict__ candidate,
             const float* __restrict__ b1) {
    __shared__ __align__(16) float sWeff[HH * DD];   // 9216 B
    __shared__ float sCterm[HH];
    __shared__ float sCand[DD];
    __shared__ float sH[224 * 37];                   // 33152 B, pad-37 conflict-free

    const int b = blockIdx.x;
    const int t = threadIdx.x;

    if (t < DD) sCand[t] = candidate[b * DD + t];
    __syncthreads();

    // Weff^T[h][d] = (B-C)^T[h][d] + cand[d] * D^T[h][d]
    for (int i = t; i < HH * DD; i += 224) {
        int d = i & 63;
        sWeff[i] = g_WbcT[i] + sCand[d] * g_WdT[i];
    }
    // cterm[h] = b1[h] + sum_d cand[d] * (A+C)^T[h][d]
    if (t < HH) {
        float c = b1[t];
        #pragma unroll
        for (int d = 0; d < DD; ++d) c += sCand[d] * g_WacT[t * DD + d];
        sCterm[t] = c;
    }
    __syncthreads();

    const bool active = (t < SS);
    float2 hreg[DD / 2];
    if (active) {
        const float4* rp = reinterpret_cast<const float4*>(
            history + ((size_t)b * SS + t) * DD);
        #pragma unroll
        for (int i = 0; i < 16; ++i) {
            float4 v = rp[i];
            hreg[2 * i]     = make_float2(v.x, v.y);
            hreg[2 * i + 1] = make_float2(v.z, v.w);
        }
    } else {
        #pragma unroll
        for (int i = 0; i < DD / 2; ++i) hreg[i] = make_float2(0.f, 0.f);
    }

    float* myrow = sH + t * 37;
    #pragma unroll 4
    for (int h = 0; h < HH; ++h) {
        const float4* wp = reinterpret_cast<const float4*>(sWeff + h * DD);
        float2 a0 = make_float2(0.f, 0.f);
        float2 a1 = make_float2(0.f, 0.f);
        #pragma unroll
        for (int i = 0; i < 16; ++i) {
            float4 wv = wp[i];   // broadcast LDS.128, conflict-free
            ffma2(a0, hreg[2 * i],     make_float2(wv.x, wv.y));
            ffma2(a1, hreg[2 * i + 1], make_float2(wv.z, wv.w));
        }
        float val = a0.x + a0.y + a1.x + a1.y + sCterm[h];
        if (!active) val = 0.f;
        myrow[h] = val;          // stride-37 scalar STS: conflict-free
    }
    __syncthreads();

    // 36 threads column-reduce (sum, sumsq); 4-way unrolled partials
    if (t < HH) {
        float S0 = 0.f, S1 = 0.f, S2 = 0.f, S3 = 0.f;
        float Q0 = 0.f, Q1 = 0.f, Q2 = 0.f, Q3 = 0.f;
        #pragma unroll 4
        for (int s = 0; s < 224; s += 4) {
            float v0 = sH[(s + 0) * 37 + t];
            float v1 = sH[(s + 1) * 37 + t];
            float v2 = sH[(s + 2) * 37 + t];
            float v3 = sH[(s + 3) * 37 + t];
            S0 += v0; Q0 = fmaf(v0, v0, Q0);
            S1 += v1; Q1 = fmaf(v1, v1, Q1);
            S2 += v2; Q2 = fmaf(v2, v2, Q2);
            S3 += v3; Q3 = fmaf(v3, v3, Q3);
        }
        g_partS[b * HH + t] = (S0 + S1) + (S2 + S3);
        g_partQ[b * HH + t] = (Q0 + Q1) + (Q2 + Q3);
    }
}

// ---------------- kernel 2: reduce partials, finalize BN affine ----------------
__global__ void k_finalize(const float* __restrict__ gamma,
                           const float* __restrict__ beta) {
    __shared__ float rS[256], rQ[256];
    const int f = blockIdx.x;
    const int t = threadIdx.x;
    float S = 0.f, Q = 0.f;
    for (int b = t; b < BB; b += 256) {
        S += g_partS[b * HH + f];
        Q += g_partQ[b * HH + f];
    }
    rS[t] = S; rQ[t] = Q;
    __syncthreads();
    for (int off = 128; off; off >>= 1) {
        if (t < off) { rS[t] += rS[t + off]; rQ[t] += rQ[t + off]; }
        __syncthreads();
    }
    if (t == 0) {
        const float n = (float)NROWS;
        float mu  = rS[0] / n;
        float var = rQ[0] / n - mu * mu;
        float is  = rsqrtf(var + BN_EPS);
        float a   = is * gamma[f];
        g_scaleA[f] = a;
        g_shiftC[f] = beta[f] - mu * a;
    }
}

// ---------------- kernel 3: recompute h (BN folded), Dice -> w -> pooling ----------------
__global__ __launch_bounds__(224, 2)
void k_pass2(const float* __restrict__ history,
             const float* __restrict__ candidate,
             const float* __restrict__ b1,
             const float* __restrict__ alpha,
             const float* __restrict__ W2,
             const float* __restrict__ b2,
             float* __restrict__ out) {
    __shared__ __align__(16) float sWeff[HH * DD];   // BN-scaled Weff^T
    __shared__ float sCterm[HH];                     // BN-folded bias
    __shared__ float sCand[DD];
    __shared__ float sW2[HH];
    __shared__ float sW[224];                        // per-s attention weight
    __shared__ __align__(16) float sPool[14 * 64];   // per-sgroup pooled partials
    __shared__ float sAlpha, sB2;

    const int b = blockIdx.x;
    const int t = threadIdx.x;

    if (t < DD) sCand[t] = candidate[b * DD + t];
    if (t == 0) { sAlpha = alpha[0]; sB2 = b2[0]; }
    __syncthreads();

    // Weff'^T[h][d] = (WbcT + cand*WdT) * scaleA[h]   (BN scale folded in)
    for (int i = t; i < HH * DD; i += 224) {
        int h = i >> 6, d = i & 63;
        sWeff[i] = (g_WbcT[i] + sCand[d] * g_WdT[i]) * g_scaleA[h];
    }
    // cterm'[h] = (b1[h] + cand@(A+C)[h]) * scaleA[h] + shiftC[h]
    if (t < HH) {
        float c = b1[t];
        #pragma unroll
        for (int d = 0; d < DD; ++d) c += sCand[d] * g_WacT[t * DD + d];
        sCterm[t] = c * g_scaleA[t] + g_shiftC[t];
        sW2[t] = W2[t];
    }
    __syncthreads();

    // ---- phase A: per-row y (post-BN), Dice, w[s] ----
    const bool active = (t < SS);
    {
        float2 hreg[DD / 2];
        if (active) {
            const float4* rp = reinterpret_cast<const float4*>(
                history + ((size_t)b * SS + t) * DD);
            #pragma unroll
            for (int i = 0; i < 16; ++i) {
                float4 v = rp[i];
                hreg[2 * i]     = make_float2(v.x, v.y);
                hreg[2 * i + 1] = make_float2(v.z, v.w);
            }
        } else {
            #pragma unroll
            for (int i = 0; i < DD / 2; ++i) hreg[i] = make_float2(0.f, 0.f);
        }

        float y[HH];
        #pragma unroll 4
        for (int h = 0; h < HH; ++h) {
            const float4* wp = reinterpret_cast<const float4*>(sWeff + h * DD);
            float2 a0 = make_float2(0.f, 0.f);
            float2 a1 = make_float2(0.f, 0.f);
            #pragma unroll
            for (int i = 0; i < 16; ++i) {
                float4 wv = wp[i];
                ffma2(a0, hreg[2 * i],     make_float2(wv.x, wv.y));
                ffma2(a1, hreg[2 * i + 1], make_float2(wv.z, wv.w));
            }
            y[h] = a0.x + a0.y + a1.x + a1.y + sCterm[h];
        }

        float w = 0.f;
        if (active) {
            float sy = 0.f, sy2 = 0.f;
            #pragma unroll
            for (int j = 0; j < HH; ++j) { sy += y[j]; sy2 = fmaf(y[j], y[j], sy2); }
            const float inv = 1.f / (float)HH;
            float avg = sy * inv;
            float var = sy2 * inv - avg * avg;
            float is  = rsqrtf(var + DICE_EPS);
            float al  = sAlpha;
            float acc = sB2;
            #pragma unroll
            for (int j = 0; j < HH; ++j) {
                float xs = (y[j] - avg) * is;
                float ps = 1.f / (1.f + __expf(-xs));
                float f  = ps + (1.f - ps) * al;
                acc = fmaf(y[j] * f, sW2[j], acc);
            }
            w = acc;
        }
        sW[t] = w;
    }
    __syncthreads();

    // ---- phase B: pooled[d] = sum_s w[s]*hist[s][d]; transposed mapping ----
    {
        const int sg = t >> 4;       // 0..13
        const int d4 = t & 15;       // float4 index 0..15
        const float4* hp = reinterpret_cast<const float4*>(
            history + (size_t)b * SS * DD);
        float4 acc = make_float4(0.f, 0.f, 0.f, 0.f);
        #pragma unroll
        for (int i = 0; i < 15; ++i) {
            int s = sg + 14 * i;
            if (s < SS) {
                float wv = sW[s];
                float4 v = hp[s * 16 + d4];     // L2-hot re-read
                acc.x = fmaf(wv, v.x, acc.x);
                acc.y = fmaf(wv, v.y, acc.y);
                acc.z = fmaf(wv, v.z, acc.z);
                acc.w = fmaf(wv, v.w, acc.w);
            }
        }
        reinterpret_cast<float4*>(sPool)[sg * 16 + d4] = acc;
    }
    __syncthreads();

    if (t < DD) {
        float s = 0.f;
        #pragma unroll
        for (int g = 0; g < 14; ++g) s += sPool[g * 64 + t];
        out[b * DD + t] = s;
    }
}

// ---------------- launch ----------------
extern "C" void kernel_launch(void* const* d_in, const int* in_sizes, int n_in,
                              void* d_out, int out_size) {
    const float* history   = (const float*)d_in[0];
    const float* candidate = (const float*)d_in[1];
    const float* W1        = (const float*)d_in[2];
    const float* b1        = (const float*)d_in[3];
    const float* gamma     = (const float*)d_in[4];
    const float* beta      = (const float*)d_in[5];
    const float* alpha     = (const float*)d_in[6];
    const float* W2        = (const float*)d_in[7];
    const float* b2        = (const float*)d_in[8];
    float* out = (float*)d_out;

    k_init<<<1, 256>>>(W1);
    k_pass1<<<BB, 224>>>(history, candidate, b1);
    k_finalize<<<HH, 256>>>(gamma, beta);
    k_pass2<<<BB, 224>>>(history, candidate, b1, alpha, W2, b2, out);
}

// round 5
// speedup vs baseline: 1.0027x; 1.0027x over previous
#include <cuda_runtime.h>
#include <cuda_bf16.h>
#include <string.h>

// Problem constants
#define BB 4096
#define SS 200
#define DD 64
#define HH 36
#define NROWS (BB * SS)          // 819200
#define BN_EPS 1e-5f
#define DICE_EPS 1e-3f

// ---------------- device scratch (no cudaMalloc allowed) ----------------
__device__ float g_WbcT[HH * DD];         // (B - C)^T   [h][d]
__device__ float g_WdT [HH * DD];         // D^T         [h][d]
__device__ float g_WacT[HH * DD];         // (A + C)^T   [h][d]
__device__ float g_partS[BB * HH];        // per-block per-feature partial sums
__device__ float g_partQ[BB * HH];        // per-block per-feature partial sumsq
__device__ float g_scaleA[HH];            // istd * gamma
__device__ float g_shiftC[HH];            // beta - mu * istd * gamma

// packed f32x2 FMA (Blackwell double-rate fp32 path; ptxas won't auto-fuse)
__device__ __forceinline__ void ffma2(float2& d, float2 a, float2 b) {
    unsigned long long ua, ub, ud;
    memcpy(&ua, &a, 8); memcpy(&ub, &b, 8); memcpy(&ud, &d, 8);
    asm("fma.rn.f32x2 %0, %1, %2, %0;" : "+l"(ud) : "l"(ua), "l"(ub));
    memcpy(&d, &ud, 8);
}

// ---------------- kernel 0: precompute weight combos ----------------
__global__ void k_init(const float* __restrict__ W1) {
    int t = threadIdx.x;
    for (int i = t; i < HH * DD; i += 256) {
        int h = i >> 6, d = i & 63;
        // W1 is [256][36] row-major; blocks: A rows 0-63, B 64-127, C 128-191, D 192-255
        float wA = W1[(d      ) * HH + h];
        float wB = W1[(64  + d) * HH + h];
        float wC = W1[(128 + d) * HH + h];
        float wD = W1[(192 + d) * HH + h];
        g_WbcT[i] = wB - wC;
        g_WdT [i] = wD;
        g_WacT[i] = wA + wC;
    }
}

// ---------------- kernel 1: per-b GEMM (200x64x36) -> smem tile -> stats only ----------------
__global__ __launch_bounds__(224, 3)
void k_pass1(const float* __restrict__ history,
             const float* __restrict__ candidate,
             const float* __restrict__ b1) {
    __shared__ __align__(16) float sWeff[HH * DD];   // 9216 B
    __shared__ float sCterm[HH];
    __shared__ float sCand[DD];
    __shared__ float sH[224 * 37];                   // 33152 B, pad-37 conflict-free

    const int b = blockIdx.x;
    const int t = threadIdx.x;

    if (t < DD) sCand[t] = candidate[b * DD + t];
    __syncthreads();

    // Weff^T[h][d] = (B-C)^T[h][d] + cand[d] * D^T[h][d]
    for (int i = t; i < HH * DD; i += 224) {
        int d = i & 63;
        sWeff[i] = g_WbcT[i] + sCand[d] * g_WdT[i];
    }
    // cterm[h] = b1[h] + sum_d cand[d] * (A+C)^T[h][d]
    if (t < HH) {
        float c = b1[t];
        #pragma unroll
        for (int d = 0; d < DD; ++d) c += sCand[d] * g_WacT[t * DD + d];
        sCterm[t] = c;
    }
    __syncthreads();

    const bool active = (t < SS);
    float2 hreg[DD / 2];
    if (active) {
        const float4* rp = reinterpret_cast<const float4*>(
            history + ((size_t)b * SS + t) * DD);
        #pragma unroll
        for (int i = 0; i < 16; ++i) {
            float4 v = rp[i];
            hreg[2 * i]     = make_float2(v.x, v.y);
            hreg[2 * i + 1] = make_float2(v.z, v.w);
        }
    } else {
        #pragma unroll
        for (int i = 0; i < DD / 2; ++i) hreg[i] = make_float2(0.f, 0.f);
    }

    float* myrow = sH + t * 37;
    #pragma unroll 4
    for (int h = 0; h < HH; ++h) {
        const float4* wp = reinterpret_cast<const float4*>(sWeff + h * DD);
        float2 a0 = make_float2(0.f, 0.f);
        float2 a1 = make_float2(0.f, 0.f);
        #pragma unroll
        for (int i = 0; i < 16; ++i) {
            float4 wv = wp[i];   // broadcast LDS.128, conflict-free
            ffma2(a0, hreg[2 * i],     make_float2(wv.x, wv.y));
            ffma2(a1, hreg[2 * i + 1], make_float2(wv.z, wv.w));
        }
        float val = a0.x + a0.y + a1.x + a1.y + sCterm[h];
        if (!active) val = 0.f;
        myrow[h] = val;          // stride-37 scalar STS: conflict-free
    }
    __syncthreads();

    // 36 threads column-reduce (sum, sumsq); 4-way unrolled partials
    if (t < HH) {
        float S0 = 0.f, S1 = 0.f, S2 = 0.f, S3 = 0.f;
        float Q0 = 0.f, Q1 = 0.f, Q2 = 0.f, Q3 = 0.f;
        #pragma unroll 4
        for (int s = 0; s < 224; s += 4) {
            float v0 = sH[(s + 0) * 37 + t];
            float v1 = sH[(s + 1) * 37 + t];
            float v2 = sH[(s + 2) * 37 + t];
            float v3 = sH[(s + 3) * 37 + t];
            S0 += v0; Q0 = fmaf(v0, v0, Q0);
            S1 += v1; Q1 = fmaf(v1, v1, Q1);
            S2 += v2; Q2 = fmaf(v2, v2, Q2);
            S3 += v3; Q3 = fmaf(v3, v3, Q3);
        }
        g_partS[b * HH + t] = (S0 + S1) + (S2 + S3);
        g_partQ[b * HH + t] = (Q0 + Q1) + (Q2 + Q3);
    }
}

// ---------------- kernel 2: reduce partials, finalize BN affine ----------------
__global__ void k_finalize(const float* __restrict__ gamma,
                           const float* __restrict__ beta) {
    __shared__ float rS[256], rQ[256];
    const int f = blockIdx.x;
    const int t = threadIdx.x;
    float S = 0.f, Q = 0.f;
    for (int b = t; b < BB; b += 256) {
        S += g_partS[b * HH + f];
        Q += g_partQ[b * HH + f];
    }
    rS[t] = S; rQ[t] = Q;
    __syncthreads();
    for (int off = 128; off; off >>= 1) {
        if (t < off) { rS[t] += rS[t + off]; rQ[t] += rQ[t + off]; }
        __syncthreads();
    }
    if (t == 0) {
        const float n = (float)NROWS;
        float mu  = rS[0] / n;
        float var = rQ[0] / n - mu * mu;
        float is  = rsqrtf(var + BN_EPS);
        float a   = is * gamma[f];
        g_scaleA[f] = a;
        g_shiftC[f] = beta[f] - mu * a;
    }
}

// ---------------- kernel 3: recompute h (BN folded), Dice -> w -> pooling ----------------
__global__ __launch_bounds__(224, 2)
void k_pass2(const float* __restrict__ history,
             const float* __restrict__ candidate,
             const float* __restrict__ b1,
             const float* __restrict__ alpha,
             const float* __restrict__ W2,
             const float* __restrict__ b2,
             float* __restrict__ out) {
    __shared__ __align__(16) float sWeff[HH * DD];   // BN-scaled Weff^T
    __shared__ float sCterm[HH];                     // BN-folded bias
    __shared__ float sCand[DD];
    __shared__ float sW2[HH];
    __shared__ float sW[224];                        // per-s attention weight
    __shared__ __align__(16) float sPool[14 * 64];   // per-sgroup pooled partials
    __shared__ float sAlpha, sB2;

    const int b = blockIdx.x;
    const int t = threadIdx.x;

    if (t < DD) sCand[t] = candidate[b * DD + t];
    if (t == 0) { sAlpha = alpha[0]; sB2 = b2[0]; }
    __syncthreads();

    // Weff'^T[h][d] = (WbcT + cand*WdT) * scaleA[h]   (BN scale folded in)
    for (int i = t; i < HH * DD; i += 224) {
        int h = i >> 6, d = i & 63;
        sWeff[i] = (g_WbcT[i] + sCand[d] * g_WdT[i]) * g_scaleA[h];
    }
    // cterm'[h] = (b1[h] + cand@(A+C)[h]) * scaleA[h] + shiftC[h]
    if (t < HH) {
        float c = b1[t];
        #pragma unroll
        for (int d = 0; d < DD; ++d) c += sCand[d] * g_WacT[t * DD + d];
        sCterm[t] = c * g_scaleA[t] + g_shiftC[t];
        sW2[t] = W2[t];
    }
    __syncthreads();

    // ---- phase A: per-row y (post-BN), Dice, w[s] ----
    const bool active = (t < SS);
    {
        float2 hreg[DD / 2];
        if (active) {
            const float4* rp = reinterpret_cast<const float4*>(
                history + ((size_t)b * SS + t) * DD);
            #pragma unroll
            for (int i = 0; i < 16; ++i) {
                float4 v = rp[i];
                hreg[2 * i]     = make_float2(v.x, v.y);
                hreg[2 * i + 1] = make_float2(v.z, v.w);
            }
        } else {
            #pragma unroll
            for (int i = 0; i < DD / 2; ++i) hreg[i] = make_float2(0.f, 0.f);
        }

        float y[HH];
        #pragma unroll 4
        for (int h = 0; h < HH; ++h) {
            const float4* wp = reinterpret_cast<const float4*>(sWeff + h * DD);
            float2 a0 = make_float2(0.f, 0.f);
            float2 a1 = make_float2(0.f, 0.f);
            #pragma unroll
            for (int i = 0; i < 16; ++i) {
                float4 wv = wp[i];
                ffma2(a0, hreg[2 * i],     make_float2(wv.x, wv.y));
                ffma2(a1, hreg[2 * i + 1], make_float2(wv.z, wv.w));
            }
            y[h] = a0.x + a0.y + a1.x + a1.y + sCterm[h];
        }

        float w = 0.f;
        if (active) {
            float sy = 0.f, sy2 = 0.f;
            #pragma unroll
            for (int j = 0; j < HH; ++j) { sy += y[j]; sy2 = fmaf(y[j], y[j], sy2); }
            const float inv = 1.f / (float)HH;
            float avg = sy * inv;
            float var = sy2 * inv - avg * avg;
            float is  = rsqrtf(var + DICE_EPS);
            float al  = sAlpha;
            float acc = sB2;
            #pragma unroll
            for (int j = 0; j < HH; ++j) {
                float xs = (y[j] - avg) * is;
                float ps = 1.f / (1.f + __expf(-xs));
                float f  = ps + (1.f - ps) * al;
                acc = fmaf(y[j] * f, sW2[j], acc);
            }
            w = acc;
        }
        sW[t] = w;
    }
    __syncthreads();

    // ---- phase B: pooled[d] = sum_s w[s]*hist[s][d]; transposed mapping ----
    {
        const int sg = t >> 4;       // 0..13
        const int d4 = t & 15;       // float4 index 0..15
        const float4* hp = reinterpret_cast<const float4*>(
            history + (size_t)b * SS * DD);
        float4 acc = make_float4(0.f, 0.f, 0.f, 0.f);
        #pragma unroll
        for (int i = 0; i < 15; ++i) {
            int s = sg + 14 * i;
            if (s < SS) {
                float wv = sW[s];
                float4 v = hp[s * 16 + d4];     // L2-hot re-read
                acc.x = fmaf(wv, v.x, acc.x);
                acc.y = fmaf(wv, v.y, acc.y);
                acc.z = fmaf(wv, v.z, acc.z);
                acc.w = fmaf(wv, v.w, acc.w);
            }
        }
        reinterpret_cast<float4*>(sPool)[sg * 16 + d4] = acc;
    }
    __syncthreads();

    if (t < DD) {
        float s = 0.f;
        #pragma unroll
        for (int g = 0; g < 14; ++g) s += sPool[g * 64 + t];
        out[b * DD + t] = s;
    }
}

// ---------------- launch ----------------
extern "C" void kernel_launch(void* const* d_in, const int* in_sizes, int n_in,
                              void* d_out, int out_size) {
    const float* history   = (const float*)d_in[0];
    const float* candidate = (const float*)d_in[1];
    const float* W1        = (const float*)d_in[2];
    const float* b1        = (const float*)d_in[3];
    const float* gamma     = (const float*)d_in[4];
    const float* beta      = (const float*)d_in[5];
    const float* alpha     = (const float*)d_in[6];
    const float* W2        = (const float*)d_in[7];
    const float* b2        = (const float*)d_in[8];
    float* out = (float*)d_out;

    k_init<<<1, 256>>>(W1);
    k_pass1<<<BB, 224>>>(history, candidate, b1);
    k_finalize<<<HH, 256>>>(gamma, beta);
    k_pass2<<<BB, 224>>>(history, candidate, b1, alpha, W2, b2, out);
}